// round 3
// baseline (speedup 1.0000x reference)
#include <cuda_runtime.h>

#define NODES_MAX 200000
#define CC 16
#define HH 64
#define DINN 40
#define WT_STRIDE 66
#define WX_STRIDE 42
#define NEGV (-1e9f)

// scratch for pooled output of kernel 1 (no cudaMalloc allowed)
__device__ float g_pooled[(size_t)NODES_MAX * HH];

__device__ __forceinline__ unsigned long long ffma2(unsigned long long a,
                                                    unsigned long long b,
                                                    unsigned long long c) {
    unsigned long long d;
    asm("fma.rn.f32x2 %0, %1, %2, %3;" : "=l"(d) : "l"(a), "l"(b), "l"(c));
    return d;
}
__device__ __forceinline__ unsigned long long pack2(float x, float y) {
    unsigned long long r;
    asm("mov.b64 %0, {%1, %2};" : "=l"(r) : "f"(x), "f"(y));
    return r;
}
__device__ __forceinline__ float hadd2(unsigned long long v) {
    float lo, hi;
    asm("mov.b64 {%0, %1}, %2;" : "=f"(lo), "=f"(hi) : "l"(v));
    return lo + hi;
}

// ---------------------------------------------------------------------------
// Kernel 1: GAT over children + ELU + masked max-pool -> g_pooled[N][64]
// One warp per node (grid-stride). Lane owns output columns k=l and k=l+32.
// ---------------------------------------------------------------------------
__global__ __launch_bounds__(256, 2) void k1_attn(
    const float* __restrict__ ch_g,   // [N,16,64]
    const float* __restrict__ A_g,    // [N,16,16]
    const int*   __restrict__ cnt_g,  // [N]
    const float* __restrict__ W_g,    // [64,64]
    const float* __restrict__ asrc_g, // [64]
    const float* __restrict__ adst_g, // [64]
    int N)
{
    extern __shared__ float smem[];
    float* Wt      = smem;                         // [64][66] transposed W
    float* chs_all = Wt + HH * WT_STRIDE;          // 8 * [16*64]
    float* As_all  = chs_all + 8 * CC * HH;        // 8 * [256]
    float* at_all  = As_all + 8 * CC * CC;         // 8 * [256]
    float* sd_all  = at_all + 8 * CC * CC;         // 8 * [32]

    const int tid = threadIdx.x;
    const int l = tid & 31, w = tid >> 5;
    float* chs = chs_all + w * (CC * HH);
    float* As  = As_all + w * (CC * CC);
    float* at  = at_all + w * (CC * CC);
    float* sd  = sd_all + w * (2 * CC);

    // Transpose W into smem: Wt[k][h] = W[h][k], padded stride 66 (bank-safe)
    for (int i = tid; i < HH * HH; i += 256) {
        int h = i >> 6, k = i & 63;
        Wt[k * WT_STRIDE + h] = W_g[i];
    }
    const float as0 = asrc_g[l], as1 = asrc_g[l + 32];
    const float ad0 = adst_g[l], ad1 = adst_g[l + 32];
    __syncthreads();

    const int warp_id = blockIdx.x * 8 + w;
    const int nwarp = gridDim.x * 8;

    for (int n = warp_id; n < N; n += nwarp) {
        __syncwarp();
        // ---- stage child_hiddens [16x64] and A_c [16x16] into smem ----
        const float4* c4 = (const float4*)(ch_g + (size_t)n * CC * HH);
        float4* cd = (float4*)chs;
        #pragma unroll
        for (int it = 0; it < 8; ++it) cd[l + 32 * it] = c4[l + 32 * it];
        const float4* a4 = (const float4*)(A_g + (size_t)n * CC * CC);
        float4* adw = (float4*)As;
        adw[l] = a4[l];
        adw[l + 32] = a4[l + 32];
        const int cnt = cnt_g[n];
        __syncwarp();

        // ---- Phase A: Wh[c][k] = sum_h ch[c][h] * W[h][k]  (FFMA2, h-paired)
        unsigned long long acc0[CC], acc1[CC];
        #pragma unroll
        for (int c = 0; c < CC; ++c) { acc0[c] = 0ull; acc1[c] = 0ull; }
        for (int t = 0; t < 8; ++t) {   // h tile of 8
            unsigned long long w0[4], w1[4];
            #pragma unroll
            for (int p = 0; p < 4; ++p) {
                w0[p] = *(const unsigned long long*)(Wt + l * WT_STRIDE + 8 * t + 2 * p);
                w1[p] = *(const unsigned long long*)(Wt + (l + 32) * WT_STRIDE + 8 * t + 2 * p);
            }
            #pragma unroll
            for (int c = 0; c < CC; ++c) {
                ulonglong2 xa = *(const ulonglong2*)(chs + c * HH + 8 * t);
                ulonglong2 xb = *(const ulonglong2*)(chs + c * HH + 8 * t + 4);
                acc0[c] = ffma2(xa.x, w0[0], acc0[c]);
                acc0[c] = ffma2(xa.y, w0[1], acc0[c]);
                acc0[c] = ffma2(xb.x, w0[2], acc0[c]);
                acc0[c] = ffma2(xb.y, w0[3], acc0[c]);
                acc1[c] = ffma2(xa.x, w1[0], acc1[c]);
                acc1[c] = ffma2(xa.y, w1[1], acc1[c]);
                acc1[c] = ffma2(xb.x, w1[2], acc1[c]);
                acc1[c] = ffma2(xb.y, w1[3], acc1[c]);
            }
        }
        float Wh0[CC], Wh1[CC];
        #pragma unroll
        for (int c = 0; c < CC; ++c) { Wh0[c] = hadd2(acc0[c]); Wh1[c] = hadd2(acc1[c]); }

        // ---- Phase B: src[c] = Wh[c].a_src, dst[c] = Wh[c].a_dst (warp reduce)
        for (int c = 0; c < cnt; ++c) {
            float ps = Wh0[c] * as0 + Wh1[c] * as1;
            float pd = Wh0[c] * ad0 + Wh1[c] * ad1;
            #pragma unroll
            for (int s = 16; s; s >>= 1) {
                ps += __shfl_xor_sync(0xffffffffu, ps, s);
                pd += __shfl_xor_sync(0xffffffffu, pd, s);
            }
            if (l == 0) { sd[c] = ps; sd[CC + c] = pd; }
        }
        __syncwarp();

        // ---- Phase C: masked leaky-relu + softmax over j, 2 rows per pass
        {
            const int half = l >> 4, j = l & 15;
            const int qmax = (cnt + 1) >> 1;
            for (int q = 0; q < qmax; ++q) {
                int row = 2 * q + half;
                float e = sd[row] + sd[CC + j];
                e = e > 0.0f ? e : 0.2f * e;
                bool m = (As[row * CC + j] > 0.5f) && (j < cnt) && (row < cnt);
                float v = m ? e : NEGV;
                float mx = v;
                #pragma unroll
                for (int s = 8; s; s >>= 1)
                    mx = fmaxf(mx, __shfl_xor_sync(0xffffffffu, mx, s));
                float p = __expf(v - mx);   // all-masked row -> exp(0)=1 -> uniform 1/16
                float sum = p;
                #pragma unroll
                for (int s = 8; s; s >>= 1)
                    sum += __shfl_xor_sync(0xffffffffu, sum, s);
                at[row * CC + j] = __fdividef(p, sum);
            }
        }
        __syncwarp();

        // ---- Phase D: h_msg = elu(attn @ Wh); max-pool over valid rows ----
        unsigned long long wp0[8], wp1[8];
        #pragma unroll
        for (int jj = 0; jj < 8; ++jj) {
            wp0[jj] = pack2(Wh0[2 * jj], Wh0[2 * jj + 1]);
            wp1[jj] = pack2(Wh1[2 * jj], Wh1[2 * jj + 1]);
        }
        float m0 = NEGV, m1 = NEGV;
        for (int row = 0; row < cnt; ++row) {
            const ulonglong2* ar = (const ulonglong2*)(at + row * CC);
            unsigned long long h0 = 0ull, h1 = 0ull;
            #pragma unroll
            for (int pp = 0; pp < 4; ++pp) {
                ulonglong2 a = ar[pp];
                h0 = ffma2(a.x, wp0[2 * pp], h0);
                h0 = ffma2(a.y, wp0[2 * pp + 1], h0);
                h1 = ffma2(a.x, wp1[2 * pp], h1);
                h1 = ffma2(a.y, wp1[2 * pp + 1], h1);
            }
            float s0 = hadd2(h0), s1 = hadd2(h1);
            s0 = s0 > 0.0f ? s0 : expm1f(s0);
            s1 = s1 > 0.0f ? s1 : expm1f(s1);
            m0 = fmaxf(m0, s0);
            m1 = fmaxf(m1, s1);
        }
        g_pooled[(size_t)n * HH + l] = m0;
        g_pooled[(size_t)n * HH + 32 + l] = m1;
    }
}

// ---------------------------------------------------------------------------
// Kernel 2: GRU update. One warp per node; lane owns k=l and k=l+32 of each
// of the 3 gates (6 dot products per lane), FFMA2 over paired h.
// ---------------------------------------------------------------------------
__global__ __launch_bounds__(256, 2) void k2_gru(
    const float* __restrict__ x_g,    // [N,40]
    const float* __restrict__ Wx_g,   // [40,192]
    const float* __restrict__ Whg_g,  // [64,192]
    const float* __restrict__ b_g,    // [192]
    float* __restrict__ out_g,        // [N,64]
    int N)
{
    extern __shared__ float smem[];
    float* Wxt = smem;                        // [192][42] transposed Wx
    float* Wht = Wxt + 192 * WX_STRIDE;       // [192][66] transposed Wh_g
    float* xs_all = Wht + 192 * WT_STRIDE;    // 8 * [48]
    float* ps_all = xs_all + 8 * 48;          // 8 * [64]

    const int tid = threadIdx.x;
    const int l = tid & 31, w = tid >> 5;
    float* xs = xs_all + w * 48;
    float* ps = ps_all + w * HH;

    for (int i = tid; i < DINN * 192; i += 256) {
        int h = i / 192, t = i % 192;
        Wxt[t * WX_STRIDE + h] = Wx_g[i];
    }
    for (int i = tid; i < HH * 192; i += 256) {
        int h = i / 192, t = i % 192;
        Wht[t * WT_STRIDE + h] = Whg_g[i];
    }
    float bb[6];
    #pragma unroll
    for (int g = 0; g < 3; ++g) {
        bb[2 * g]     = b_g[g * 64 + l];
        bb[2 * g + 1] = b_g[g * 64 + l + 32];
    }
    __syncthreads();

    const int warp_id = blockIdx.x * 8 + w;
    const int nwarp = gridDim.x * 8;

    for (int n = warp_id; n < N; n += nwarp) {
        __syncwarp();
        if (l < 10)
            ((float4*)xs)[l] = ((const float4*)(x_g + (size_t)n * DINN))[l];
        ((float2*)ps)[l] = ((const float2*)(g_pooled + (size_t)n * HH))[l];
        __syncwarp();

        unsigned long long acc[6];
        #pragma unroll
        for (int d = 0; d < 6; ++d) acc[d] = 0ull;

        // gh = pooled @ Wh_g  (64 h = 32 pairs, 4 chunks of 8 pairs)
        #pragma unroll
        for (int chk = 0; chk < 4; ++chk) {
            unsigned long long pu[8];
            #pragma unroll
            for (int p = 0; p < 4; ++p) {
                ulonglong2 v = *(const ulonglong2*)(ps + chk * 16 + 4 * p);
                pu[2 * p] = v.x; pu[2 * p + 1] = v.y;
            }
            #pragma unroll
            for (int g = 0; g < 3; ++g)
            #pragma unroll
            for (int kk = 0; kk < 2; ++kk) {
                const int t = g * 64 + l + 32 * kk;
                const float* wb = Wht + t * WT_STRIDE + chk * 16;
                const int d = 2 * g + kk;
                #pragma unroll
                for (int p = 0; p < 8; ++p)
                    acc[d] = ffma2(pu[p], *(const unsigned long long*)(wb + 2 * p), acc[d]);
            }
        }
        float gh[6];
        #pragma unroll
        for (int d = 0; d < 6; ++d) { gh[d] = hadd2(acc[d]); acc[d] = 0ull; }

        // gx = x @ Wx  (40 h = 20 pairs, 2 chunks of 10 pairs)
        #pragma unroll
        for (int chk = 0; chk < 2; ++chk) {
            unsigned long long xu[10];
            #pragma unroll
            for (int p = 0; p < 5; ++p) {
                ulonglong2 v = *(const ulonglong2*)(xs + chk * 20 + 4 * p);
                xu[2 * p] = v.x; xu[2 * p + 1] = v.y;
            }
            #pragma unroll
            for (int g = 0; g < 3; ++g)
            #pragma unroll
            for (int kk = 0; kk < 2; ++kk) {
                const int t = g * 64 + l + 32 * kk;
                const float* wb = Wxt + t * WX_STRIDE + chk * 20;
                const int d = 2 * g + kk;
                #pragma unroll
                for (int p = 0; p < 10; ++p)
                    acc[d] = ffma2(xu[p], *(const unsigned long long*)(wb + 2 * p), acc[d]);
            }
        }

        const float p0 = ps[l], p1 = ps[l + 32];
        #pragma unroll
        for (int kk = 0; kk < 2; ++kk) {
            float xz = hadd2(acc[kk])     + bb[kk];
            float xr = hadd2(acc[2 + kk]) + bb[2 + kk];
            float xn = hadd2(acc[4 + kk]) + bb[4 + kk];
            float z = 1.0f / (1.0f + __expf(-(xz + gh[kk])));
            float r = 1.0f / (1.0f + __expf(-(xr + gh[2 + kk])));
            float a = xn + r * gh[4 + kk];
            float ex = __expf(2.0f * a);
            float th = 1.0f - __fdividef(2.0f, ex + 1.0f);  // tanh, inf-safe
            float pool = kk ? p1 : p0;
            out_g[(size_t)n * HH + l + 32 * kk] = (1.0f - z) * th + z * pool;
        }
    }
}

// ---------------------------------------------------------------------------
extern "C" void kernel_launch(void* const* d_in, const int* in_sizes, int n_in,
                              void* d_out, int out_size) {
    const float* node_features = (const float*)d_in[0];
    const float* child_hiddens = (const float*)d_in[1];
    const float* A_c           = (const float*)d_in[2];
    const int*   child_count   = (const int*)d_in[3];
    const float* W             = (const float*)d_in[4];
    const float* a_src         = (const float*)d_in[5];
    const float* a_dst         = (const float*)d_in[6];
    const float* Wx            = (const float*)d_in[7];
    const float* Wh_g          = (const float*)d_in[8];
    const float* b             = (const float*)d_in[9];
    float* out = (float*)d_out;
    const int N = in_sizes[3];

    const int k1_smem = (HH * WT_STRIDE + 8 * CC * HH + 8 * CC * CC +
                         8 * CC * CC + 8 * 2 * CC) * (int)sizeof(float);
    const int k2_smem = (192 * WX_STRIDE + 192 * WT_STRIDE + 8 * 48 + 8 * HH) *
                        (int)sizeof(float);

    cudaFuncSetAttribute(k1_attn, cudaFuncAttributeMaxDynamicSharedMemorySize, k1_smem);
    cudaFuncSetAttribute(k2_gru, cudaFuncAttributeMaxDynamicSharedMemorySize, k2_smem);

    const int grid = 304;  // 152 SMs * 2 resident CTAs
    k1_attn<<<grid, 256, k1_smem>>>(child_hiddens, A_c, child_count, W,
                                    a_src, a_dst, N);
    k2_gru<<<grid, 256, k2_smem>>>(node_features, Wx, Wh_g, b, out, N);
}

// round 4
// speedup vs baseline: 1.3487x; 1.3487x over previous
#include <cuda_runtime.h>

#define NODES_MAX 200000
#define CC 16
#define HH 64
#define DINN 40
#define CH_STRIDE 66   // child_hiddens smem row stride (conflict-free for lane-c reads)
#define AS_STRIDE 17   // A_c smem row stride
#define AT_STRIDE 18   // attn smem row stride (8B-aligned rows + conflict-free STS)
#define WT_STRIDE 66
#define WX_STRIDE 42
#define NEGV (-1e9f)

// scratch for pooled output of kernel 1 (no cudaMalloc allowed)
__device__ float g_pooled[(size_t)NODES_MAX * HH];

__device__ __forceinline__ unsigned long long ffma2(unsigned long long a,
                                                    unsigned long long b,
                                                    unsigned long long c) {
    unsigned long long d;
    asm("fma.rn.f32x2 %0, %1, %2, %3;" : "=l"(d) : "l"(a), "l"(b), "l"(c));
    return d;
}
__device__ __forceinline__ unsigned long long pack2(float x, float y) {
    unsigned long long r;
    asm("mov.b64 %0, {%1, %2};" : "=l"(r) : "f"(x), "f"(y));
    return r;
}
__device__ __forceinline__ float hadd2(unsigned long long v) {
    float lo, hi;
    asm("mov.b64 {%0, %1}, %2;" : "=f"(lo), "=f"(hi) : "l"(v));
    return lo + hi;
}
__device__ __forceinline__ unsigned long long lds64(const float* p) {
    return *(const unsigned long long*)p;
}

// ---------------------------------------------------------------------------
// Kernel 1: GAT over children + ELU + masked max-pool -> g_pooled[N][64]
// One warp per node (grid-stride). Lane owns output columns k=l and k=l+32.
// No warp shuffles anywhere in the hot loop.
// ---------------------------------------------------------------------------
__global__ __launch_bounds__(256, 2) void k1_attn(
    const float* __restrict__ ch_g,   // [N,16,64]
    const float* __restrict__ A_g,    // [N,16,16]
    const int*   __restrict__ cnt_g,  // [N]
    const float* __restrict__ W_g,    // [64,64]
    const float* __restrict__ asrc_g, // [64]
    const float* __restrict__ adst_g, // [64]
    int N)
{
    extern __shared__ float smem[];
    float* Wt      = smem;                           // [64][66] transposed W
    float* was     = Wt + HH * WT_STRIDE;            // [128]: wa | wd
    float* chs_all = was + 128;                      // 8 * [16*66]
    float* As_all  = chs_all + 8 * CC * CH_STRIDE;   // 8 * [16*17]
    float* at_all  = As_all + 8 * CC * AS_STRIDE;    // 8 * [16*18]
    float* sd_all  = at_all + 8 * CC * AT_STRIDE;    // 8 * [32]

    const int tid = threadIdx.x;
    const int l = tid & 31, w = tid >> 5;
    float* chs = chs_all + w * (CC * CH_STRIDE);
    float* As  = As_all + w * (CC * AS_STRIDE);
    float* at  = at_all + w * (CC * AT_STRIDE);
    float* sd  = sd_all + w * (2 * CC);

    // Transpose W into smem: Wt[k][h] = W[h][k]
    for (int i = tid; i < HH * HH; i += 256) {
        int h = i >> 6, k = i & 63;
        Wt[k * WT_STRIDE + h] = W_g[i];
    }
    __syncthreads();
    // Precompute wa = W @ a_src, wd = W @ a_dst  (once per CTA)
    if (tid < 128) {
        const int half = tid >> 6, h = tid & 63;
        const float* av = half ? adst_g : asrc_g;
        float s = 0.0f;
        for (int k = 0; k < HH; ++k) s += Wt[k * WT_STRIDE + h] * av[k];
        was[half * 64 + h] = s;
    }
    __syncthreads();

    const int warp_id = blockIdx.x * 8 + w;
    const int nwarp = gridDim.x * 8;

    for (int n = warp_id; n < N; n += nwarp) {
        __syncwarp();
        // ---- stage child_hiddens [16 rows, stride 66] and A_c [16, stride 17]
        {
            const float4* c4 = (const float4*)(ch_g + (size_t)n * CC * HH);
            #pragma unroll
            for (int it = 0; it < 8; ++it) {
                int i = l + 32 * it;           // float4 index 0..255
                float4 v = c4[i];
                int c = i >> 4, h0 = (i & 15) << 2;
                float* dst = chs + c * CH_STRIDE + h0;
                *(unsigned long long*)(dst)     = pack2(v.x, v.y);
                *(unsigned long long*)(dst + 2) = pack2(v.z, v.w);
            }
            const float4* a4 = (const float4*)(A_g + (size_t)n * CC * CC);
            #pragma unroll
            for (int it = 0; it < 2; ++it) {
                int i = l + 32 * it;           // float4 index 0..63
                float4 v = a4[i];
                int r = i >> 2, c0 = (i & 3) << 2;
                float* dst = As + r * AS_STRIDE + c0;
                dst[0] = v.x; dst[1] = v.y; dst[2] = v.z; dst[3] = v.w;
            }
        }
        const int cnt = cnt_g[n];
        __syncwarp();

        // ---- Phase A: Wh[c][k] = sum_h ch[c][h] * W[h][k]  (FFMA2, h-paired)
        unsigned long long acc0[CC], acc1[CC];
        #pragma unroll
        for (int c = 0; c < CC; ++c) { acc0[c] = 0ull; acc1[c] = 0ull; }
        for (int t = 0; t < 8; ++t) {   // h tile of 8
            unsigned long long w0[4], w1[4];
            #pragma unroll
            for (int p = 0; p < 4; ++p) {
                w0[p] = lds64(Wt + l * WT_STRIDE + 8 * t + 2 * p);
                w1[p] = lds64(Wt + (l + 32) * WT_STRIDE + 8 * t + 2 * p);
            }
            #pragma unroll
            for (int c = 0; c < CC; ++c) {
                const float* xb = chs + c * CH_STRIDE + 8 * t;
                unsigned long long x0 = lds64(xb), x1 = lds64(xb + 2);
                unsigned long long x2 = lds64(xb + 4), x3 = lds64(xb + 6);
                acc0[c] = ffma2(x0, w0[0], acc0[c]);
                acc0[c] = ffma2(x1, w0[1], acc0[c]);
                acc0[c] = ffma2(x2, w0[2], acc0[c]);
                acc0[c] = ffma2(x3, w0[3], acc0[c]);
                acc1[c] = ffma2(x0, w1[0], acc1[c]);
                acc1[c] = ffma2(x1, w1[1], acc1[c]);
                acc1[c] = ffma2(x2, w1[2], acc1[c]);
                acc1[c] = ffma2(x3, w1[3], acc1[c]);
            }
        }
        float Wh0[CC], Wh1[CC];
        #pragma unroll
        for (int c = 0; c < CC; ++c) { Wh0[c] = hadd2(acc0[c]); Wh1[c] = hadd2(acc1[c]); }

        // ---- Phase B: lane c -> src[c] = ch[c].wa ; lane c+16 -> dst[c] = ch[c].wd
        float my_sd;
        {
            const int c = l & 15;
            const float* xrow = chs + c * CH_STRIDE;
            const float* wrow = was + (l >> 4) * 64;
            unsigned long long a0 = 0ull, a1 = 0ull, a2 = 0ull, a3 = 0ull;
            #pragma unroll
            for (int p = 0; p < 8; ++p) {
                a0 = ffma2(lds64(xrow + 8 * p),     lds64(wrow + 8 * p),     a0);
                a1 = ffma2(lds64(xrow + 8 * p + 2), lds64(wrow + 8 * p + 2), a1);
                a2 = ffma2(lds64(xrow + 8 * p + 4), lds64(wrow + 8 * p + 4), a2);
                a3 = ffma2(lds64(xrow + 8 * p + 6), lds64(wrow + 8 * p + 6), a3);
            }
            my_sd = hadd2(a0) + hadd2(a1) + hadd2(a2) + hadd2(a3);
            sd[l] = my_sd;
        }
        __syncwarp();

        // ---- Phase C: row-parallel masked leaky-relu softmax (lane r = row r)
        if (l < cnt && l < 16) {
            const int r = l;
            const float srcr = my_sd;
            float ev[CC];
            float mx = NEGV;
            #pragma unroll
            for (int j = 0; j < CC; ++j) {
                float e = srcr + sd[CC + j];
                e = e > 0.0f ? e : 0.2f * e;
                bool m = (As[r * AS_STRIDE + j] > 0.5f) && (j < cnt);
                float v = m ? e : NEGV;
                ev[j] = v;
                mx = fmaxf(mx, v);
            }
            float* atr = at + r * AT_STRIDE;
            if (mx < -1e8f) {
                // fully masked row -> uniform 1/16 (matches reference softmax of all-NEG)
                #pragma unroll
                for (int j = 0; j < CC; ++j) atr[j] = 0.0625f;
            } else {
                float pv[CC];
                float sum = 0.0f;
                #pragma unroll
                for (int j = 0; j < CC; ++j) {
                    float p = (ev[j] > -1e8f) ? __expf(ev[j] - mx) : 0.0f;
                    pv[j] = p;
                    sum += p;
                }
                const float inv = __fdividef(1.0f, sum);
                #pragma unroll
                for (int j = 0; j < CC; ++j) atr[j] = pv[j] * inv;
            }
        }
        __syncwarp();

        // ---- Phase D: h_msg = elu(attn @ Wh); max-pool over valid rows ----
        unsigned long long wp0[8], wp1[8];
        #pragma unroll
        for (int jj = 0; jj < 8; ++jj) {
            wp0[jj] = pack2(Wh0[2 * jj], Wh0[2 * jj + 1]);
            wp1[jj] = pack2(Wh1[2 * jj], Wh1[2 * jj + 1]);
        }
        float m0 = NEGV, m1 = NEGV;
        for (int row = 0; row < cnt; ++row) {
            const float* ar = at + row * AT_STRIDE;
            unsigned long long h0 = 0ull, h1 = 0ull;
            #pragma unroll
            for (int pp = 0; pp < 8; ++pp) {
                unsigned long long a = lds64(ar + 2 * pp);
                h0 = ffma2(a, wp0[pp], h0);
                h1 = ffma2(a, wp1[pp], h1);
            }
            float s0 = hadd2(h0), s1 = hadd2(h1);
            s0 = s0 > 0.0f ? s0 : (__expf(s0) - 1.0f);
            s1 = s1 > 0.0f ? s1 : (__expf(s1) - 1.0f);
            m0 = fmaxf(m0, s0);
            m1 = fmaxf(m1, s1);
        }
        g_pooled[(size_t)n * HH + l] = m0;
        g_pooled[(size_t)n * HH + 32 + l] = m1;
    }
}

// ---------------------------------------------------------------------------
// Kernel 2: GRU update. One warp per FOUR nodes: each lane-distinct weight
// pair loaded from smem once is reused by 4 nodes' broadcast x-operands,
// cutting LDS weight traffic 4x (was the 94.5% L1 bottleneck).
// ---------------------------------------------------------------------------
__global__ __launch_bounds__(256, 2) void k2_gru(
    const float* __restrict__ x_g,    // [N,40]
    const float* __restrict__ Wx_g,   // [40,192]
    const float* __restrict__ Whg_g,  // [64,192]
    const float* __restrict__ b_g,    // [192]
    float* __restrict__ out_g,        // [N,64]
    int N)
{
    extern __shared__ float smem[];
    float* Wxt = smem;                        // [192][42] transposed Wx
    float* Wht = Wxt + 192 * WX_STRIDE;       // [192][66] transposed Wh_g
    float* xs_all = Wht + 192 * WT_STRIDE;    // 8 * [4*40]
    float* ps_all = xs_all + 8 * 160;         // 8 * [4*64]

    const int tid = threadIdx.x;
    const int l = tid & 31, w = tid >> 5;
    float* xs = xs_all + w * 160;
    float* ps = ps_all + w * 256;

    for (int i = tid; i < DINN * 192; i += 256) {
        int h = i / 192, t = i % 192;
        Wxt[t * WX_STRIDE + h] = Wx_g[i];
    }
    for (int i = tid; i < HH * 192; i += 256) {
        int h = i / 192, t = i % 192;
        Wht[t * WT_STRIDE + h] = Whg_g[i];
    }
    float bb[6];
    #pragma unroll
    for (int g = 0; g < 3; ++g) {
        bb[2 * g]     = b_g[g * 64 + l];
        bb[2 * g + 1] = b_g[g * 64 + l + 32];
    }
    __syncthreads();

    const int warp_id = blockIdx.x * 8 + w;
    const int nwarp = gridDim.x * 8;

    for (int n0 = warp_id * 4; n0 < N; n0 += nwarp * 4) {
        __syncwarp();
        // ---- stage 4 nodes of x [4*40] and pooled [4*64] (contiguous rows)
        {
            const int remx = min(160, (N - n0) * DINN);
            const float4* xg4 = (const float4*)(x_g + (size_t)n0 * DINN);
            if (l * 4 < remx)        ((float4*)xs)[l] = xg4[l];
            if ((l + 32) * 4 < remx) ((float4*)xs)[l + 32] = xg4[l + 32];
            const int remp = min(256, (N - n0) * HH);
            const float4* pg4 = (const float4*)(g_pooled + (size_t)n0 * HH);
            if (l * 4 < remp)        ((float4*)ps)[l] = pg4[l];
            if ((l + 32) * 4 < remp) ((float4*)ps)[l + 32] = pg4[l + 32];
        }
        __syncwarp();

        unsigned long long acc[24];   // [m][d], d = g*2+kk
        #pragma unroll
        for (int d = 0; d < 24; ++d) acc[d] = 0ull;

        // ---- gh = pooled @ Wh_g : 8 chunks of 4 h-pairs ----
        #pragma unroll
        for (int chk = 0; chk < 8; ++chk) {
            unsigned long long xm[4][4];
            #pragma unroll
            for (int m = 0; m < 4; ++m)
                #pragma unroll
                for (int p = 0; p < 4; ++p)
                    xm[m][p] = lds64(ps + m * 64 + chk * 8 + 2 * p);
            #pragma unroll
            for (int g = 0; g < 3; ++g)
                #pragma unroll
                for (int kk = 0; kk < 2; ++kk) {
                    const float* wb = Wht + (g * 64 + l + 32 * kk) * WT_STRIDE + chk * 8;
                    unsigned long long w0 = lds64(wb),     w1 = lds64(wb + 2);
                    unsigned long long w2 = lds64(wb + 4), w3 = lds64(wb + 6);
                    const int d = g * 2 + kk;
                    #pragma unroll
                    for (int m = 0; m < 4; ++m) {
                        acc[m * 6 + d] = ffma2(xm[m][0], w0, acc[m * 6 + d]);
                        acc[m * 6 + d] = ffma2(xm[m][1], w1, acc[m * 6 + d]);
                        acc[m * 6 + d] = ffma2(xm[m][2], w2, acc[m * 6 + d]);
                        acc[m * 6 + d] = ffma2(xm[m][3], w3, acc[m * 6 + d]);
                    }
                }
        }
        float gh[24];
        #pragma unroll
        for (int d = 0; d < 24; ++d) { gh[d] = hadd2(acc[d]); acc[d] = 0ull; }

        // ---- gx = x @ Wx : 5 chunks of 4 h-pairs ----
        #pragma unroll
        for (int chk = 0; chk < 5; ++chk) {
            unsigned long long xm[4][4];
            #pragma unroll
            for (int m = 0; m < 4; ++m)
                #pragma unroll
                for (int p = 0; p < 4; ++p)
                    xm[m][p] = lds64(xs + m * 40 + chk * 8 + 2 * p);
            #pragma unroll
            for (int g = 0; g < 3; ++g)
                #pragma unroll
                for (int kk = 0; kk < 2; ++kk) {
                    const float* wb = Wxt + (g * 64 + l + 32 * kk) * WX_STRIDE + chk * 8;
                    unsigned long long w0 = lds64(wb),     w1 = lds64(wb + 2);
                    unsigned long long w2 = lds64(wb + 4), w3 = lds64(wb + 6);
                    const int d = g * 2 + kk;
                    #pragma unroll
                    for (int m = 0; m < 4; ++m) {
                        acc[m * 6 + d] = ffma2(xm[m][0], w0, acc[m * 6 + d]);
                        acc[m * 6 + d] = ffma2(xm[m][1], w1, acc[m * 6 + d]);
                        acc[m * 6 + d] = ffma2(xm[m][2], w2, acc[m * 6 + d]);
                        acc[m * 6 + d] = ffma2(xm[m][3], w3, acc[m * 6 + d]);
                    }
                }
        }

        // ---- epilogue per node ----
        #pragma unroll
        for (int m = 0; m < 4; ++m) {
            if (n0 + m < N) {
                #pragma unroll
                for (int kk = 0; kk < 2; ++kk) {
                    float xz = hadd2(acc[m * 6 + kk])     + bb[kk];
                    float xr = hadd2(acc[m * 6 + 2 + kk]) + bb[2 + kk];
                    float xn = hadd2(acc[m * 6 + 4 + kk]) + bb[4 + kk];
                    float z = 1.0f / (1.0f + __expf(-(xz + gh[m * 6 + kk])));
                    float r = 1.0f / (1.0f + __expf(-(xr + gh[m * 6 + 2 + kk])));
                    float a = xn + r * gh[m * 6 + 4 + kk];
                    float ex = __expf(2.0f * a);
                    float th = 1.0f - __fdividef(2.0f, ex + 1.0f);  // tanh, inf-safe
                    float pool = ps[m * 64 + l + 32 * kk];
                    out_g[(size_t)(n0 + m) * HH + l + 32 * kk] = (1.0f - z) * th + z * pool;
                }
            }
        }
    }
}

// ---------------------------------------------------------------------------
extern "C" void kernel_launch(void* const* d_in, const int* in_sizes, int n_in,
                              void* d_out, int out_size) {
    const float* node_features = (const float*)d_in[0];
    const float* child_hiddens = (const float*)d_in[1];
    const float* A_c           = (const float*)d_in[2];
    const int*   child_count   = (const int*)d_in[3];
    const float* W             = (const float*)d_in[4];
    const float* a_src         = (const float*)d_in[5];
    const float* a_dst         = (const float*)d_in[6];
    const float* Wx            = (const float*)d_in[7];
    const float* Wh_g          = (const float*)d_in[8];
    const float* b             = (const float*)d_in[9];
    float* out = (float*)d_out;
    const int N = in_sizes[3];

    const int k1_smem = (HH * WT_STRIDE + 128 + 8 * CC * CH_STRIDE +
                         8 * CC * AS_STRIDE + 8 * CC * AT_STRIDE + 8 * 32) *
                        (int)sizeof(float);
    const int k2_smem = (192 * WX_STRIDE + 192 * WT_STRIDE + 8 * 160 + 8 * 256) *
                        (int)sizeof(float);

    cudaFuncSetAttribute(k1_attn, cudaFuncAttributeMaxDynamicSharedMemorySize, k1_smem);
    cudaFuncSetAttribute(k2_gru, cudaFuncAttributeMaxDynamicSharedMemorySize, k2_smem);

    const int grid = 304;  // 152 SMs * 2 resident CTAs
    k1_attn<<<grid, 256, k1_smem>>>(child_hiddens, A_c, child_count, W,
                                    a_src, a_dst, N);
    k2_gru<<<grid, 256, k2_smem>>>(node_features, Wx, Wh_g, b, out, N);
}

// round 5
// speedup vs baseline: 1.6216x; 1.2023x over previous
#include <cuda_runtime.h>

#define NODES_MAX 200000
#define CC 16
#define HH 64
#define DINN 40
#define CH_STRIDE 68   // child smem row stride (floats): 272B, 16B-aligned rows
#define AS_STRIDE 20   // A_c smem row stride (floats): 80B, 16B-aligned rows
#define WT_STRIDE 66
#define WX_STRIDE 42
#define NEGV (-1e9f)

// scratch for pooled output of kernel 1 (no cudaMalloc allowed)
__device__ float g_pooled[(size_t)NODES_MAX * HH];

__device__ __forceinline__ unsigned long long ffma2(unsigned long long a,
                                                    unsigned long long b,
                                                    unsigned long long c) {
    unsigned long long d;
    asm("fma.rn.f32x2 %0, %1, %2, %3;" : "=l"(d) : "l"(a), "l"(b), "l"(c));
    return d;
}
__device__ __forceinline__ unsigned long long pack2(float x, float y) {
    unsigned long long r;
    asm("mov.b64 %0, {%1, %2};" : "=l"(r) : "f"(x), "f"(y));
    return r;
}
__device__ __forceinline__ float hadd2(unsigned long long v) {
    float lo, hi;
    asm("mov.b64 {%0, %1}, %2;" : "=f"(lo), "=f"(hi) : "l"(v));
    return lo + hi;
}
__device__ __forceinline__ unsigned long long lds64(const float* p) {
    return *(const unsigned long long*)p;
}
__device__ __forceinline__ void cpa16(unsigned dst, const void* src) {
    asm volatile("cp.async.cg.shared.global [%0], [%1], 16;" :: "r"(dst), "l"(src));
}

// issue async copy of one node's child_hiddens [16x64] + A_c [16x16] into
// padded smem buffers, then commit the group. 10 x 16B per lane.
__device__ __forceinline__ void prefetch_node(const float* __restrict__ ch_g,
                                              const float* __restrict__ A_g,
                                              int n, float* chb, float* Asb, int l) {
    const char* csrc = (const char*)(ch_g + (size_t)n * (CC * HH));
    unsigned chs_s = (unsigned)__cvta_generic_to_shared(chb);
    #pragma unroll
    for (int it = 0; it < 8; ++it) {
        int i = l + 32 * it;            // 16B chunk id, 0..255
        int c = i >> 4, k = i & 15;     // child row, chunk within row
        cpa16(chs_s + c * (CH_STRIDE * 4) + k * 16, csrc + i * 16);
    }
    const char* asrc = (const char*)(A_g + (size_t)n * (CC * CC));
    unsigned as_s = (unsigned)__cvta_generic_to_shared(Asb);
    #pragma unroll
    for (int it = 0; it < 2; ++it) {
        int j = l + 32 * it;            // 16B chunk id, 0..63
        int r = j >> 2, q = j & 3;
        cpa16(as_s + r * (AS_STRIDE * 4) + q * 16, asrc + j * 16);
    }
    asm volatile("cp.async.commit_group;");
}

// ---------------------------------------------------------------------------
// Kernel 1: GAT over children + ELU + masked max-pool -> g_pooled[N][64]
// One warp per node, cp.async double-buffered prefetch, phase order B->C->A->D
// so Phase A (the Wh GEMM) only runs over cnt_eff children.
// ---------------------------------------------------------------------------
__global__ __launch_bounds__(256, 2) void k1_attn(
    const float* __restrict__ ch_g,   // [N,16,64]
    const float* __restrict__ A_g,    // [N,16,16]
    const int*   __restrict__ cnt_g,  // [N]
    const float* __restrict__ W_g,    // [64,64]
    const float* __restrict__ asrc_g, // [64]
    const float* __restrict__ adst_g, // [64]
    int N)
{
    extern __shared__ float smem[];
    float* Wt      = smem;                               // [64][66] transposed W
    float* was     = Wt + HH * WT_STRIDE;                // [128]: wa | wd
    float* chs_all = was + 128;                          // 8 * [2][16*68]
    float* As_all  = chs_all + 8 * 2 * CC * CH_STRIDE;   // 8 * [2][16*20]
    float* sd_all  = As_all + 8 * 2 * CC * AS_STRIDE;    // 8 * [32]

    const int tid = threadIdx.x;
    const int l = tid & 31, w = tid >> 5;
    float* chs_b = chs_all + w * (2 * CC * CH_STRIDE);
    float* As_b  = As_all + w * (2 * CC * AS_STRIDE);
    float* sd    = sd_all + w * (2 * CC);

    // Transpose W into smem: Wt[k][h] = W[h][k]
    for (int i = tid; i < HH * HH; i += 256) {
        int h = i >> 6, k = i & 63;
        Wt[k * WT_STRIDE + h] = W_g[i];
    }
    __syncthreads();
    // Precompute wa = W @ a_src, wd = W @ a_dst  (once per CTA)
    if (tid < 128) {
        const int half = tid >> 6, h = tid & 63;
        const float* av = half ? adst_g : asrc_g;
        float s = 0.0f;
        for (int k = 0; k < HH; ++k) s += Wt[k * WT_STRIDE + h] * av[k];
        was[half * 64 + h] = s;
    }
    __syncthreads();

    const int warp_id = blockIdx.x * 8 + w;
    const int nwarp = gridDim.x * 8;

    int n = warp_id;
    if (n >= N) return;
    prefetch_node(ch_g, A_g, n, chs_b, As_b, l);
    int cnt_c = cnt_g[n];
    int p = 0;

    for (; n < N; n += nwarp, p ^= 1) {
        // prefetch next node into the other buffer
        const int nn = (n + nwarp < N) ? (n + nwarp) : (N - 1);
        float* chs_n = chs_b + (p ^ 1) * (CC * CH_STRIDE);
        float* As_n  = As_b + (p ^ 1) * (CC * AS_STRIDE);
        prefetch_node(ch_g, A_g, nn, chs_n, As_n, l);
        const int cnt_n = cnt_g[nn];

        asm volatile("cp.async.wait_group 1;");
        __syncwarp();

        float* chs = chs_b + p * (CC * CH_STRIDE);
        float* As  = As_b + p * (CC * AS_STRIDE);
        const int cnt = cnt_c;

        // ---- Phase B: lane c -> src[c]=ch[c].wa ; lane c+16 -> dst[c]=ch[c].wd
        float my_sd;
        {
            const int c = l & 15;
            const float* xrow = chs + c * CH_STRIDE;
            const float* wrow = was + (l >> 4) * 64;
            unsigned long long a0 = 0ull, a1 = 0ull, a2 = 0ull, a3 = 0ull;
            #pragma unroll
            for (int q = 0; q < 8; ++q) {
                a0 = ffma2(lds64(xrow + 8 * q),     lds64(wrow + 8 * q),     a0);
                a1 = ffma2(lds64(xrow + 8 * q + 2), lds64(wrow + 8 * q + 2), a1);
                a2 = ffma2(lds64(xrow + 8 * q + 4), lds64(wrow + 8 * q + 4), a2);
                a3 = ffma2(lds64(xrow + 8 * q + 6), lds64(wrow + 8 * q + 6), a3);
            }
            my_sd = hadd2(a0) + hadd2(a1) + hadd2(a2) + hadd2(a3);
            sd[l] = my_sd;
        }
        __syncwarp();

        // ---- Phase C: row-parallel masked leaky-relu softmax, deferred scale.
        // attn (unscaled) overwrites As row in place; sd[r] holds 1/rowsum.
        bool am = false;
        if (l < cnt && l < 16) {
            const int r = l;
            const float srcr = my_sd;
            float ev[CC];
            float mx = NEGV;
            #pragma unroll
            for (int j = 0; j < CC; ++j) {
                float e = srcr + sd[CC + j];
                e = e > 0.0f ? e : 0.2f * e;
                bool m = (As[r * AS_STRIDE + j] > 0.5f) && (j < cnt);
                float v = m ? e : NEGV;
                ev[j] = v;
                mx = fmaxf(mx, v);
            }
            float* atr = As + r * AS_STRIDE;
            am = (mx < -1e8f);
            if (am) {
                // fully masked row -> uniform 1/16 over all 16 children
                #pragma unroll
                for (int j = 0; j < CC; ++j) atr[j] = 1.0f;
                sd[r] = 0.0625f;
            } else {
                float sum = 0.0f;
                #pragma unroll
                for (int j = 0; j < CC; ++j) {
                    float pj = (ev[j] > -1e8f) ? __expf(ev[j] - mx) : 0.0f;
                    atr[j] = pj;
                    sum += pj;
                }
                sd[r] = __fdividef(1.0f, sum);
            }
        }
        const unsigned bal = __ballot_sync(0xffffffffu, am);
        const int cnt_eff = bal ? CC : cnt;   // need padded Wh only if uniform row
        __syncwarp();

        // ---- Phase A: Wh[c][k] = sum_h ch[c][h]*W[h][k], c < cnt_eff only ----
        unsigned long long acc0[CC], acc1[CC];
        #pragma unroll
        for (int c = 0; c < CC; ++c) { acc0[c] = 0ull; acc1[c] = 0ull; }
        for (int t = 0; t < 8; ++t) {
            unsigned long long w0[4], w1[4];
            #pragma unroll
            for (int q = 0; q < 4; ++q) {
                w0[q] = lds64(Wt + l * WT_STRIDE + 8 * t + 2 * q);
                w1[q] = lds64(Wt + (l + 32) * WT_STRIDE + 8 * t + 2 * q);
            }
            #pragma unroll
            for (int cb = 0; cb < 4; ++cb) {
                if (cb * 4 < cnt_eff) {     // warp-uniform chunk skip
                    #pragma unroll
                    for (int i = 0; i < 4; ++i) {
                        const int c = cb * 4 + i;
                        const float* xb = chs + c * CH_STRIDE + 8 * t;
                        unsigned long long x0 = lds64(xb), x1 = lds64(xb + 2);
                        unsigned long long x2 = lds64(xb + 4), x3 = lds64(xb + 6);
                        acc0[c] = ffma2(x0, w0[0], acc0[c]);
                        acc0[c] = ffma2(x1, w0[1], acc0[c]);
                        acc0[c] = ffma2(x2, w0[2], acc0[c]);
                        acc0[c] = ffma2(x3, w0[3], acc0[c]);
                        acc1[c] = ffma2(x0, w1[0], acc1[c]);
                        acc1[c] = ffma2(x1, w1[1], acc1[c]);
                        acc1[c] = ffma2(x2, w1[2], acc1[c]);
                        acc1[c] = ffma2(x3, w1[3], acc1[c]);
                    }
                }
            }
        }
        float Wh0[CC], Wh1[CC];
        #pragma unroll
        for (int c = 0; c < CC; ++c) { Wh0[c] = hadd2(acc0[c]); Wh1[c] = hadd2(acc1[c]); }

        // ---- Phase D: h_msg = elu(scale*(attn_unscaled @ Wh)); masked max-pool
        unsigned long long wp0[8], wp1[8];
        #pragma unroll
        for (int jj = 0; jj < 8; ++jj) {
            wp0[jj] = pack2(Wh0[2 * jj], Wh0[2 * jj + 1]);
            wp1[jj] = pack2(Wh1[2 * jj], Wh1[2 * jj + 1]);
        }
        float m0 = NEGV, m1 = NEGV;
        for (int row = 0; row < cnt; ++row) {
            const float* ar = As + row * AS_STRIDE;
            const float scale = sd[row];
            unsigned long long h0 = 0ull, h1 = 0ull;
            #pragma unroll
            for (int pp = 0; pp < 8; ++pp) {
                unsigned long long a = lds64(ar + 2 * pp);
                h0 = ffma2(a, wp0[pp], h0);
                h1 = ffma2(a, wp1[pp], h1);
            }
            float s0 = hadd2(h0) * scale, s1 = hadd2(h1) * scale;
            s0 = s0 > 0.0f ? s0 : (__expf(s0) - 1.0f);
            s1 = s1 > 0.0f ? s1 : (__expf(s1) - 1.0f);
            m0 = fmaxf(m0, s0);
            m1 = fmaxf(m1, s1);
        }
        g_pooled[(size_t)n * HH + l] = m0;
        g_pooled[(size_t)n * HH + 32 + l] = m1;

        cnt_c = cnt_n;
        __syncwarp();   // all lanes done with buffer p before next prefetch hits it
    }
}

// ---------------------------------------------------------------------------
// Kernel 2: GRU update. One warp per FOUR nodes (weight LDS amortized 4x).
// Unchanged from round 4 (jointly fma + crossbar bound, near scalar floor).
// ---------------------------------------------------------------------------
__global__ __launch_bounds__(256, 2) void k2_gru(
    const float* __restrict__ x_g,    // [N,40]
    const float* __restrict__ Wx_g,   // [40,192]
    const float* __restrict__ Whg_g,  // [64,192]
    const float* __restrict__ b_g,    // [192]
    float* __restrict__ out_g,        // [N,64]
    int N)
{
    extern __shared__ float smem[];
    float* Wxt = smem;                        // [192][42] transposed Wx
    float* Wht = Wxt + 192 * WX_STRIDE;       // [192][66] transposed Wh_g
    float* xs_all = Wht + 192 * WT_STRIDE;    // 8 * [4*40]
    float* ps_all = xs_all + 8 * 160;         // 8 * [4*64]

    const int tid = threadIdx.x;
    const int l = tid & 31, w = tid >> 5;
    float* xs = xs_all + w * 160;
    float* ps = ps_all + w * 256;

    for (int i = tid; i < DINN * 192; i += 256) {
        int h = i / 192, t = i % 192;
        Wxt[t * WX_STRIDE + h] = Wx_g[i];
    }
    for (int i = tid; i < HH * 192; i += 256) {
        int h = i / 192, t = i % 192;
        Wht[t * WT_STRIDE + h] = Whg_g[i];
    }
    float bb[6];
    #pragma unroll
    for (int g = 0; g < 3; ++g) {
        bb[2 * g]     = b_g[g * 64 + l];
        bb[2 * g + 1] = b_g[g * 64 + l + 32];
    }
    __syncthreads();

    const int warp_id = blockIdx.x * 8 + w;
    const int nwarp = gridDim.x * 8;

    for (int n0 = warp_id * 4; n0 < N; n0 += nwarp * 4) {
        __syncwarp();
        {
            const int remx = min(160, (N - n0) * DINN);
            const float4* xg4 = (const float4*)(x_g + (size_t)n0 * DINN);
            if (l * 4 < remx)        ((float4*)xs)[l] = xg4[l];
            if ((l + 32) * 4 < remx) ((float4*)xs)[l + 32] = xg4[l + 32];
            const int remp = min(256, (N - n0) * HH);
            const float4* pg4 = (const float4*)(g_pooled + (size_t)n0 * HH);
            if (l * 4 < remp)        ((float4*)ps)[l] = pg4[l];
            if ((l + 32) * 4 < remp) ((float4*)ps)[l + 32] = pg4[l + 32];
        }
        __syncwarp();

        unsigned long long acc[24];   // [m][d], d = g*2+kk
        #pragma unroll
        for (int d = 0; d < 24; ++d) acc[d] = 0ull;

        // ---- gh = pooled @ Wh_g : 8 chunks of 4 h-pairs ----
        #pragma unroll
        for (int chk = 0; chk < 8; ++chk) {
            unsigned long long xm[4][4];
            #pragma unroll
            for (int m = 0; m < 4; ++m)
                #pragma unroll
                for (int q = 0; q < 4; ++q)
                    xm[m][q] = lds64(ps + m * 64 + chk * 8 + 2 * q);
            #pragma unroll
            for (int g = 0; g < 3; ++g)
                #pragma unroll
                for (int kk = 0; kk < 2; ++kk) {
                    const float* wb = Wht + (g * 64 + l + 32 * kk) * WT_STRIDE + chk * 8;
                    unsigned long long w0 = lds64(wb),     w1 = lds64(wb + 2);
                    unsigned long long w2 = lds64(wb + 4), w3 = lds64(wb + 6);
                    const int d = g * 2 + kk;
                    #pragma unroll
                    for (int m = 0; m < 4; ++m) {
                        acc[m * 6 + d] = ffma2(xm[m][0], w0, acc[m * 6 + d]);
                        acc[m * 6 + d] = ffma2(xm[m][1], w1, acc[m * 6 + d]);
                        acc[m * 6 + d] = ffma2(xm[m][2], w2, acc[m * 6 + d]);
                        acc[m * 6 + d] = ffma2(xm[m][3], w3, acc[m * 6 + d]);
                    }
                }
        }
        float gh[24];
        #pragma unroll
        for (int d = 0; d < 24; ++d) { gh[d] = hadd2(acc[d]); acc[d] = 0ull; }

        // ---- gx = x @ Wx : 5 chunks of 4 h-pairs ----
        #pragma unroll
        for (int chk = 0; chk < 5; ++chk) {
            unsigned long long xm[4][4];
            #pragma unroll
            for (int m = 0; m < 4; ++m)
                #pragma unroll
                for (int q = 0; q < 4; ++q)
                    xm[m][q] = lds64(xs + m * 40 + chk * 8 + 2 * q);
            #pragma unroll
            for (int g = 0; g < 3; ++g)
                #pragma unroll
                for (int kk = 0; kk < 2; ++kk) {
                    const float* wb = Wxt + (g * 64 + l + 32 * kk) * WX_STRIDE + chk * 8;
                    unsigned long long w0 = lds64(wb),     w1 = lds64(wb + 2);
                    unsigned long long w2 = lds64(wb + 4), w3 = lds64(wb + 6);
                    const int d = g * 2 + kk;
                    #pragma unroll
                    for (int m = 0; m < 4; ++m) {
                        acc[m * 6 + d] = ffma2(xm[m][0], w0, acc[m * 6 + d]);
                        acc[m * 6 + d] = ffma2(xm[m][1], w1, acc[m * 6 + d]);
                        acc[m * 6 + d] = ffma2(xm[m][2], w2, acc[m * 6 + d]);
                        acc[m * 6 + d] = ffma2(xm[m][3], w3, acc[m * 6 + d]);
                    }
                }
        }

        // ---- epilogue per node ----
        #pragma unroll
        for (int m = 0; m < 4; ++m) {
            if (n0 + m < N) {
                #pragma unroll
                for (int kk = 0; kk < 2; ++kk) {
                    float xz = hadd2(acc[m * 6 + kk])     + bb[kk];
                    float xr = hadd2(acc[m * 6 + 2 + kk]) + bb[2 + kk];
                    float xn = hadd2(acc[m * 6 + 4 + kk]) + bb[4 + kk];
                    float z = 1.0f / (1.0f + __expf(-(xz + gh[m * 6 + kk])));
                    float r = 1.0f / (1.0f + __expf(-(xr + gh[m * 6 + 2 + kk])));
                    float a = xn + r * gh[m * 6 + 4 + kk];
                    float ex = __expf(2.0f * a);
                    float th = 1.0f - __fdividef(2.0f, ex + 1.0f);  // tanh, inf-safe
                    float pool = ps[m * 64 + l + 32 * kk];
                    out_g[(size_t)(n0 + m) * HH + l + 32 * kk] = (1.0f - z) * th + z * pool;
                }
            }
        }
    }
}

// ---------------------------------------------------------------------------
extern "C" void kernel_launch(void* const* d_in, const int* in_sizes, int n_in,
                              void* d_out, int out_size) {
    const float* node_features = (const float*)d_in[0];
    const float* child_hiddens = (const float*)d_in[1];
    const float* A_c           = (const float*)d_in[2];
    const int*   child_count   = (const int*)d_in[3];
    const float* W             = (const float*)d_in[4];
    const float* a_src         = (const float*)d_in[5];
    const float* a_dst         = (const float*)d_in[6];
    const float* Wx            = (const float*)d_in[7];
    const float* Wh_g          = (const float*)d_in[8];
    const float* b             = (const float*)d_in[9];
    float* out = (float*)d_out;
    const int N = in_sizes[3];

    const int k1_smem = (HH * WT_STRIDE + 128 + 8 * 2 * CC * CH_STRIDE +
                         8 * 2 * CC * AS_STRIDE + 8 * 32) * (int)sizeof(float);
    const int k2_smem = (192 * WX_STRIDE + 192 * WT_STRIDE + 8 * 160 + 8 * 256) *
                        (int)sizeof(float);

    cudaFuncSetAttribute(k1_attn, cudaFuncAttributeMaxDynamicSharedMemorySize, k1_smem);
    cudaFuncSetAttribute(k2_gru, cudaFuncAttributeMaxDynamicSharedMemorySize, k2_smem);

    const int grid = 304;  // 152 SMs * 2 resident CTAs
    k1_attn<<<grid, 256, k1_smem>>>(child_hiddens, A_c, child_count, W,
                                    a_src, a_dst, N);
    k2_gru<<<grid, 256, k2_smem>>>(node_features, Wx, Wh_g, b, out, N);
}

// round 7
// speedup vs baseline: 1.6400x; 1.0114x over previous
#include <cuda_runtime.h>

#define NODES_MAX 200000
#define CC 16
#define HH 64
#define DINN 40
#define CH_STRIDE 68   // child smem row stride (floats): 272B, 16B-aligned rows
#define AS_STRIDE 20   // A_c smem row stride (floats): 80B, 16B-aligned rows
#define WT_STRIDE 68   // transposed-W stride: conflict-free 8-lane LDS.128 phases
#define WX_STRIDE 42
#define NEGV (-1e9f)

// scratch for pooled output of kernel 1 (no cudaMalloc allowed)
__device__ float g_pooled[(size_t)NODES_MAX * HH];

__device__ __forceinline__ unsigned long long ffma2(unsigned long long a,
                                                    unsigned long long b,
                                                    unsigned long long c) {
    unsigned long long d;
    asm("fma.rn.f32x2 %0, %1, %2, %3;" : "=l"(d) : "l"(a), "l"(b), "l"(c));
    return d;
}
__device__ __forceinline__ unsigned long long pack2(float x, float y) {
    unsigned long long r;
    asm("mov.b64 %0, {%1, %2};" : "=l"(r) : "f"(x), "f"(y));
    return r;
}
__device__ __forceinline__ float hadd2(unsigned long long v) {
    float lo, hi;
    asm("mov.b64 {%0, %1}, %2;" : "=f"(lo), "=f"(hi) : "l"(v));
    return lo + hi;
}
__device__ __forceinline__ unsigned long long lds64(const float* p) {
    return *(const unsigned long long*)p;
}
// 128-bit shared load as two packed f32x2 operands
__device__ __forceinline__ ulonglong2 lds128(const float* p) {
    return *(const ulonglong2*)p;
}
__device__ __forceinline__ void cpa16(unsigned dst, const void* src) {
    asm volatile("cp.async.cg.shared.global [%0], [%1], 16;" :: "r"(dst), "l"(src));
}

// issue async copy of one node's child_hiddens [16x64] + A_c [16x16] into
// padded smem buffers, then commit the group. 10 x 16B per lane.
__device__ __forceinline__ void prefetch_node(const float* __restrict__ ch_g,
                                              const float* __restrict__ A_g,
                                              int n, float* chb, float* Asb, int l) {
    const char* csrc = (const char*)(ch_g + (size_t)n * (CC * HH));
    unsigned chs_s = (unsigned)__cvta_generic_to_shared(chb);
    #pragma unroll
    for (int it = 0; it < 8; ++it) {
        int i = l + 32 * it;            // 16B chunk id, 0..255
        int c = i >> 4, k = i & 15;     // child row, chunk within row
        cpa16(chs_s + c * (CH_STRIDE * 4) + k * 16, csrc + i * 16);
    }
    const char* asrc = (const char*)(A_g + (size_t)n * (CC * CC));
    unsigned as_s = (unsigned)__cvta_generic_to_shared(Asb);
    #pragma unroll
    for (int it = 0; it < 2; ++it) {
        int j = l + 32 * it;            // 16B chunk id, 0..63
        int r = j >> 2, q = j & 3;
        cpa16(as_s + r * (AS_STRIDE * 4) + q * 16, asrc + j * 16);
    }
    asm volatile("cp.async.commit_group;");
}

// ---------------------------------------------------------------------------
// Kernel 1: GAT over children + ELU + masked max-pool -> g_pooled[N][64]
// One warp per node, cp.async double-buffered prefetch. All hot shared-memory
// traffic is 128-bit (crossbar-wavefront minimized).
// ---------------------------------------------------------------------------
__global__ __launch_bounds__(256, 2) void k1_attn(
    const float* __restrict__ ch_g,   // [N,16,64]
    const float* __restrict__ A_g,    // [N,16,16]
    const int*   __restrict__ cnt_g,  // [N]
    const float* __restrict__ W_g,    // [64,64]
    const float* __restrict__ asrc_g, // [64]
    const float* __restrict__ adst_g, // [64]
    int N)
{
    extern __shared__ float smem[];
    float* Wt      = smem;                               // [64][68] transposed W
    float* was     = Wt + HH * WT_STRIDE;                // [128]: wa | wd
    float* chs_all = was + 128;                          // 8 * [2][16*68]
    float* As_all  = chs_all + 8 * 2 * CC * CH_STRIDE;   // 8 * [2][16*20]
    float* sd_all  = As_all + 8 * 2 * CC * AS_STRIDE;    // 8 * [32]

    const int tid = threadIdx.x;
    const int l = tid & 31, w = tid >> 5;
    float* chs_b = chs_all + w * (2 * CC * CH_STRIDE);
    float* As_b  = As_all + w * (2 * CC * AS_STRIDE);
    float* sd    = sd_all + w * (2 * CC);

    // Transpose W into smem: Wt[k][h] = W[h][k]
    for (int i = tid; i < HH * HH; i += 256) {
        int h = i >> 6, k = i & 63;
        Wt[k * WT_STRIDE + h] = W_g[i];
    }
    __syncthreads();
    // Precompute wa = W @ a_src, wd = W @ a_dst  (once per CTA)
    if (tid < 128) {
        const int half = tid >> 6, h = tid & 63;
        const float* av = half ? adst_g : asrc_g;
        float s = 0.0f;
        for (int k = 0; k < HH; ++k) s += Wt[k * WT_STRIDE + h] * av[k];
        was[half * 64 + h] = s;
    }
    __syncthreads();

    const int warp_id = blockIdx.x * 8 + w;
    const int nwarp = gridDim.x * 8;

    int n = warp_id;
    if (n >= N) return;
    prefetch_node(ch_g, A_g, n, chs_b, As_b, l);
    int cnt_c = cnt_g[n];
    int p = 0;

    for (; n < N; n += nwarp, p ^= 1) {
        // prefetch next node into the other buffer
        const int nn = (n + nwarp < N) ? (n + nwarp) : (N - 1);
        float* chs_n = chs_b + (p ^ 1) * (CC * CH_STRIDE);
        float* As_n  = As_b + (p ^ 1) * (CC * AS_STRIDE);
        prefetch_node(ch_g, A_g, nn, chs_n, As_n, l);
        const int cnt_n = cnt_g[nn];

        asm volatile("cp.async.wait_group 1;");
        __syncwarp();

        float* chs = chs_b + p * (CC * CH_STRIDE);
        float* As  = As_b + p * (CC * AS_STRIDE);
        const int cnt = cnt_c;

        // ---- Phase B: lane c -> src[c]=ch[c].wa ; lane c+16 -> dst[c]=ch[c].wd
        // All loads 128-bit: row reads conflict-free at stride 68.
        float my_sd;
        {
            const int c = l & 15;
            const float* xrow = chs + c * CH_STRIDE;
            const float* wrow = was + (l >> 4) * 64;
            unsigned long long a0 = 0ull, a1 = 0ull, a2 = 0ull, a3 = 0ull;
            #pragma unroll
            for (int q = 0; q < 4; ++q) {
                ulonglong2 x0 = lds128(xrow + 16 * q);
                ulonglong2 x1 = lds128(xrow + 16 * q + 4);
                ulonglong2 x2 = lds128(xrow + 16 * q + 8);
                ulonglong2 x3 = lds128(xrow + 16 * q + 12);
                ulonglong2 w0 = lds128(wrow + 16 * q);
                ulonglong2 w1 = lds128(wrow + 16 * q + 4);
                ulonglong2 w2 = lds128(wrow + 16 * q + 8);
                ulonglong2 w3 = lds128(wrow + 16 * q + 12);
                a0 = ffma2(x0.x, w0.x, a0); a0 = ffma2(x0.y, w0.y, a0);
                a1 = ffma2(x1.x, w1.x, a1); a1 = ffma2(x1.y, w1.y, a1);
                a2 = ffma2(x2.x, w2.x, a2); a2 = ffma2(x2.y, w2.y, a2);
                a3 = ffma2(x3.x, w3.x, a3); a3 = ffma2(x3.y, w3.y, a3);
            }
            my_sd = hadd2(a0) + hadd2(a1) + hadd2(a2) + hadd2(a3);
            sd[l] = my_sd;
        }
        __syncwarp();

        // ---- Phase C: row-parallel masked leaky-relu softmax, deferred scale.
        // attn (unscaled) overwrites As row in place; sd[r] holds 1/rowsum.
        bool am = false;
        if (l < cnt && l < 16) {
            const int r = l;
            const float srcr = my_sd;
            float4 A4[4], D4[4];
            #pragma unroll
            for (int q = 0; q < 4; ++q) {
                A4[q] = ((const float4*)(As + r * AS_STRIDE))[q];
                D4[q] = ((const float4*)(sd + CC))[q];
            }
            float ev[CC];
            float mx = NEGV;
            #pragma unroll
            for (int j = 0; j < CC; ++j) {
                float aj = ((const float*)A4)[j];
                float dj = ((const float*)D4)[j];
                float e = srcr + dj;
                e = e > 0.0f ? e : 0.2f * e;
                bool m = (aj > 0.5f) && (j < cnt);
                float v = m ? e : NEGV;
                ev[j] = v;
                mx = fmaxf(mx, v);
            }
            float* atr = As + r * AS_STRIDE;
            am = (mx < -1e8f);
            if (am) {
                // fully masked row -> uniform 1/16 over all 16 children
                float4 one = make_float4(1.0f, 1.0f, 1.0f, 1.0f);
                #pragma unroll
                for (int q = 0; q < 4; ++q) ((float4*)atr)[q] = one;
                sd[r] = 0.0625f;
            } else {
                float pv[CC];
                float sum = 0.0f;
                #pragma unroll
                for (int j = 0; j < CC; ++j) {
                    float pj = (ev[j] > -1e8f) ? __expf(ev[j] - mx) : 0.0f;
                    pv[j] = pj;
                    sum += pj;
                }
                #pragma unroll
                for (int q = 0; q < 4; ++q)
                    ((float4*)atr)[q] = make_float4(pv[4 * q], pv[4 * q + 1],
                                                    pv[4 * q + 2], pv[4 * q + 3]);
                sd[r] = __fdividef(1.0f, sum);
            }
        }
        const unsigned bal = __ballot_sync(0xffffffffu, am);
        const int cnt_eff = bal ? CC : cnt;   // need padded Wh only if uniform row
        __syncwarp();

        // ---- Phase A: Wh[c][k] = sum_h ch[c][h]*W[h][k], c < cnt_eff only ----
        // weights: 128-bit lane-spread (conflict-free); x: 128-bit broadcasts.
        unsigned long long acc0[CC], acc1[CC];
        #pragma unroll
        for (int c = 0; c < CC; ++c) { acc0[c] = 0ull; acc1[c] = 0ull; }
        for (int t = 0; t < 8; ++t) {
            ulonglong2 w0a = lds128(Wt + l * WT_STRIDE + 8 * t);
            ulonglong2 w0b = lds128(Wt + l * WT_STRIDE + 8 * t + 4);
            ulonglong2 w1a = lds128(Wt + (l + 32) * WT_STRIDE + 8 * t);
            ulonglong2 w1b = lds128(Wt + (l + 32) * WT_STRIDE + 8 * t + 4);
            #pragma unroll
            for (int cb = 0; cb < 4; ++cb) {
                if (cb * 4 < cnt_eff) {     // warp-uniform chunk skip
                    #pragma unroll
                    for (int i = 0; i < 4; ++i) {
                        const int c = cb * 4 + i;
                        ulonglong2 xa = lds128(chs + c * CH_STRIDE + 8 * t);
                        ulonglong2 xb = lds128(chs + c * CH_STRIDE + 8 * t + 4);
                        acc0[c] = ffma2(xa.x, w0a.x, acc0[c]);
                        acc0[c] = ffma2(xa.y, w0a.y, acc0[c]);
                        acc0[c] = ffma2(xb.x, w0b.x, acc0[c]);
                        acc0[c] = ffma2(xb.y, w0b.y, acc0[c]);
                        acc1[c] = ffma2(xa.x, w1a.x, acc1[c]);
                        acc1[c] = ffma2(xa.y, w1a.y, acc1[c]);
                        acc1[c] = ffma2(xb.x, w1b.x, acc1[c]);
                        acc1[c] = ffma2(xb.y, w1b.y, acc1[c]);
                    }
                }
            }
        }
        float Wh0[CC], Wh1[CC];
        #pragma unroll
        for (int c = 0; c < CC; ++c) { Wh0[c] = hadd2(acc0[c]); Wh1[c] = hadd2(acc1[c]); }

        // ---- Phase D: h_msg = elu(scale*(attn_unscaled @ Wh)); masked max-pool
        unsigned long long wp0[8], wp1[8];
        #pragma unroll
        for (int jj = 0; jj < 8; ++jj) {
            wp0[jj] = pack2(Wh0[2 * jj], Wh0[2 * jj + 1]);
            wp1[jj] = pack2(Wh1[2 * jj], Wh1[2 * jj + 1]);
        }
        float m0 = NEGV, m1 = NEGV;
        for (int row = 0; row < cnt; ++row) {
            const float* ar = As + row * AS_STRIDE;
            const float scale = sd[row];
            unsigned long long h0 = 0ull, h1 = 0ull;
            #pragma unroll
            for (int pp = 0; pp < 4; ++pp) {
                ulonglong2 a = lds128(ar + 4 * pp);
                h0 = ffma2(a.x, wp0[2 * pp], h0);
                h0 = ffma2(a.y, wp0[2 * pp + 1], h0);
                h1 = ffma2(a.x, wp1[2 * pp], h1);
                h1 = ffma2(a.y, wp1[2 * pp + 1], h1);
            }
            float s0 = hadd2(h0) * scale, s1 = hadd2(h1) * scale;
            s0 = s0 > 0.0f ? s0 : (__expf(s0) - 1.0f);
            s1 = s1 > 0.0f ? s1 : (__expf(s1) - 1.0f);
            m0 = fmaxf(m0, s0);
            m1 = fmaxf(m1, s1);
        }
        g_pooled[(size_t)n * HH + l] = m0;
        g_pooled[(size_t)n * HH + 32 + l] = m1;

        cnt_c = cnt_n;
        __syncwarp();   // all lanes done with buffer p before next prefetch hits it
    }
}

// ---------------------------------------------------------------------------
// Kernel 2: GRU update. One warp per FOUR nodes (weight LDS amortized 4x).
// Unchanged (jointly fma + crossbar bound, near scalar floor).
// ---------------------------------------------------------------------------
__global__ __launch_bounds__(256, 2) void k2_gru(
    const float* __restrict__ x_g,    // [N,40]
    const float* __restrict__ Wx_g,   // [40,192]
    const float* __restrict__ Whg_g,  // [64,192]
    const float* __restrict__ b_g,    // [192]
    float* __restrict__ out_g,        // [N,64]
    int N)
{
    extern __shared__ float smem[];
    float* Wxt = smem;                        // [192][42] transposed Wx
    float* Wht = Wxt + 192 * WX_STRIDE;       // [192][66] transposed Wh_g
    float* xs_all = Wht + 192 * 66;           // 8 * [4*40]
    float* ps_all = xs_all + 8 * 160;         // 8 * [4*64]

    const int tid = threadIdx.x;
    const int l = tid & 31, w = tid >> 5;
    float* xs = xs_all + w * 160;
    float* ps = ps_all + w * 256;

    for (int i = tid; i < DINN * 192; i += 256) {
        int h = i / 192, t = i % 192;
        Wxt[t * WX_STRIDE + h] = Wx_g[i];
    }
    for (int i = tid; i < HH * 192; i += 256) {
        int h = i / 192, t = i % 192;
        Wht[t * 66 + h] = Whg_g[i];
    }
    float bb[6];
    #pragma unroll
    for (int g = 0; g < 3; ++g) {
        bb[2 * g]     = b_g[g * 64 + l];
        bb[2 * g + 1] = b_g[g * 64 + l + 32];
    }
    __syncthreads();

    const int warp_id = blockIdx.x * 8 + w;
    const int nwarp = gridDim.x * 8;

    for (int n0 = warp_id * 4; n0 < N; n0 += nwarp * 4) {
        __syncwarp();
        {
            const int remx = min(160, (N - n0) * DINN);
            const float4* xg4 = (const float4*)(x_g + (size_t)n0 * DINN);
            if (l * 4 < remx)        ((float4*)xs)[l] = xg4[l];
            if ((l + 32) * 4 < remx) ((float4*)xs)[l + 32] = xg4[l + 32];
            const int remp = min(256, (N - n0) * HH);
            const float4* pg4 = (const float4*)(g_pooled + (size_t)n0 * HH);
            if (l * 4 < remp)        ((float4*)ps)[l] = pg4[l];
            if ((l + 32) * 4 < remp) ((float4*)ps)[l + 32] = pg4[l + 32];
        }
        __syncwarp();

        unsigned long long acc[24];   // [m][d], d = g*2+kk
        #pragma unroll
        for (int d = 0; d < 24; ++d) acc[d] = 0ull;

        // ---- gh = pooled @ Wh_g : 8 chunks of 4 h-pairs ----
        #pragma unroll
        for (int chk = 0; chk < 8; ++chk) {
            unsigned long long xm[4][4];
            #pragma unroll
            for (int m = 0; m < 4; ++m)
                #pragma unroll
                for (int q = 0; q < 4; ++q)
                    xm[m][q] = lds64(ps + m * 64 + chk * 8 + 2 * q);
            #pragma unroll
            for (int g = 0; g < 3; ++g)
                #pragma unroll
                for (int kk = 0; kk < 2; ++kk) {
                    const float* wb = Wht + (g * 64 + l + 32 * kk) * 66 + chk * 8;
                    unsigned long long w0 = lds64(wb),     w1 = lds64(wb + 2);
                    unsigned long long w2 = lds64(wb + 4), w3 = lds64(wb + 6);
                    const int d = g * 2 + kk;
                    #pragma unroll
                    for (int m = 0; m < 4; ++m) {
                        acc[m * 6 + d] = ffma2(xm[m][0], w0, acc[m * 6 + d]);
                        acc[m * 6 + d] = ffma2(xm[m][1], w1, acc[m * 6 + d]);
                        acc[m * 6 + d] = ffma2(xm[m][2], w2, acc[m * 6 + d]);
                        acc[m * 6 + d] = ffma2(xm[m][3], w3, acc[m * 6 + d]);
                    }
                }
        }
        float gh[24];
        #pragma unroll
        for (int d = 0; d < 24; ++d) { gh[d] = hadd2(acc[d]); acc[d] = 0ull; }

        // ---- gx = x @ Wx : 5 chunks of 4 h-pairs ----
        #pragma unroll
        for (int chk = 0; chk < 5; ++chk) {
            unsigned long long xm[4][4];
            #pragma unroll
            for (int m = 0; m < 4; ++m)
                #pragma unroll
                for (int q = 0; q < 4; ++q)
                    xm[m][q] = lds64(xs + m * 40 + chk * 8 + 2 * q);
            #pragma unroll
            for (int g = 0; g < 3; ++g)
                #pragma unroll
                for (int kk = 0; kk < 2; ++kk) {
                    const float* wb = Wxt + (g * 64 + l + 32 * kk) * WX_STRIDE + chk * 8;
                    unsigned long long w0 = lds64(wb),     w1 = lds64(wb + 2);
                    unsigned long long w2 = lds64(wb + 4), w3 = lds64(wb + 6);
                    const int d = g * 2 + kk;
                    #pragma unroll
                    for (int m = 0; m < 4; ++m) {
                        acc[m * 6 + d] = ffma2(xm[m][0], w0, acc[m * 6 + d]);
                        acc[m * 6 + d] = ffma2(xm[m][1], w1, acc[m * 6 + d]);
                        acc[m * 6 + d] = ffma2(xm[m][2], w2, acc[m * 6 + d]);
                        acc[m * 6 + d] = ffma2(xm[m][3], w3, acc[m * 6 + d]);
                    }
                }
        }

        // ---- epilogue per node ----
        #pragma unroll
        for (int m = 0; m < 4; ++m) {
            if (n0 + m < N) {
                #pragma unroll
                for (int kk = 0; kk < 2; ++kk) {
                    float xz = hadd2(acc[m * 6 + kk])     + bb[kk];
                    float xr = hadd2(acc[m * 6 + 2 + kk]) + bb[2 + kk];
                    float xn = hadd2(acc[m * 6 + 4 + kk]) + bb[4 + kk];
                    float z = 1.0f / (1.0f + __expf(-(xz + gh[m * 6 + kk])));
                    float r = 1.0f / (1.0f + __expf(-(xr + gh[m * 6 + 2 + kk])));
                    float a = xn + r * gh[m * 6 + 4 + kk];
                    float ex = __expf(2.0f * a);
                    float th = 1.0f - __fdividef(2.0f, ex + 1.0f);  // tanh, inf-safe
                    float pool = ps[m * 64 + l + 32 * kk];
                    out_g[(size_t)(n0 + m) * HH + l + 32 * kk] = (1.0f - z) * th + z * pool;
                }
            }
        }
    }
}

// ---------------------------------------------------------------------------
extern "C" void kernel_launch(void* const* d_in, const int* in_sizes, int n_in,
                              void* d_out, int out_size) {
    const float* node_features = (const float*)d_in[0];
    const float* child_hiddens = (const float*)d_in[1];
    const float* A_c           = (const float*)d_in[2];
    const int*   child_count   = (const int*)d_in[3];
    const float* W             = (const float*)d_in[4];
    const float* a_src         = (const float*)d_in[5];
    const float* a_dst         = (const float*)d_in[6];
    const float* Wx            = (const float*)d_in[7];
    const float* Wh_g          = (const float*)d_in[8];
    const float* b             = (const float*)d_in[9];
    float* out = (float*)d_out;
    const int N = in_sizes[3];

    const int k1_smem = (HH * WT_STRIDE + 128 + 8 * 2 * CC * CH_STRIDE +
                         8 * 2 * CC * AS_STRIDE + 8 * 32) * (int)sizeof(float);
    const int k2_smem = (192 * WX_STRIDE + 192 * 66 + 8 * 160 + 8 * 256) *
                        (int)sizeof(float);

    cudaFuncSetAttribute(k1_attn, cudaFuncAttributeMaxDynamicSharedMemorySize, k1_smem);
    cudaFuncSetAttribute(k2_gru, cudaFuncAttributeMaxDynamicSharedMemorySize, k2_smem);

    const int grid = 304;  // 152 SMs * 2 resident CTAs
    k1_attn<<<grid, 256, k1_smem>>>(child_hiddens, A_c, child_count, W,
                                    a_src, a_dst, N);
    k2_gru<<<grid, 256, k2_smem>>>(node_features, Wx, Wh_g, b, out, N);
}